// round 5
// baseline (speedup 1.0000x reference)
#include <cuda_runtime.h>
#include <cuda_bf16.h>
#include <cuda_fp16.h>
#include <cstdint>
#include <cstddef>

#define NU 100000
#define NVV 100000
#define DD 128
#define RR 5
#define OO 64
#define EE 640000

#define GEMM_TILES   782                 /* ceil(100000/128) */
#define GEMM_BLOCKS  (RR * GEMM_TILES)   /* 3910 */
#define SPMM_BPR     5000                /* 640000 / 128 edges per block */
#define SPMM_BLOCKS  (RR * SPMM_BPR)     /* 25000 */
#define MERGED_GRID  (GEMM_BLOCKS + SPMM_BLOCKS) /* 28910 */

// ---------------------------------------------------------------------------
// Scratch (static device globals) — tmp now fp16
// ---------------------------------------------------------------------------
__device__ __half g_tmpU[(size_t)RR * NU * OO];   // [r][n][64]
__device__ __half g_tmpV[(size_t)RR * NVV * OO];
// Pre-swizzled bf16 B images: per relation 32KB = hi 16KB | lo 16KB.
__device__ unsigned char g_BimgU[RR * 32768];
__device__ unsigned char g_BimgV[RR * 32768];

// ---------------------------------------------------------------------------
// helpers
// ---------------------------------------------------------------------------
__device__ __forceinline__ uint32_t smem_u32(const void* p) {
    uint32_t a;
    asm("{ .reg .u64 t; cvta.to.shared.u64 t, %1; cvt.u32.u64 %0, t; }"
        : "=r"(a) : "l"(p));
    return a;
}
__device__ __forceinline__ void ldsm4(uint32_t addr, uint32_t& r0, uint32_t& r1,
                                      uint32_t& r2, uint32_t& r3) {
    asm volatile("ldmatrix.sync.aligned.m8n8.x4.shared.b16 {%0,%1,%2,%3}, [%4];"
                 : "=r"(r0), "=r"(r1), "=r"(r2), "=r"(r3) : "r"(addr));
}
__device__ __forceinline__ void mma_bf16(float* d, const uint32_t* a,
                                         uint32_t b0, uint32_t b1) {
    asm volatile(
        "mma.sync.aligned.m16n8k16.row.col.f32.bf16.bf16.f32 "
        "{%0,%1,%2,%3}, {%4,%5,%6,%7}, {%8,%9}, {%0,%1,%2,%3};"
        : "+f"(d[0]), "+f"(d[1]), "+f"(d[2]), "+f"(d[3])
        : "r"(a[0]), "r"(a[1]), "r"(a[2]), "r"(a[3]), "r"(b0), "r"(b1));
}

// ---------------------------------------------------------------------------
// cumsum weights + pack swizzled bf16 hi/lo B images (k = d, n = o)
// ---------------------------------------------------------------------------
__global__ void cumsum_pack_kernel(const float* __restrict__ wu,
                                   const float* __restrict__ wv,
                                   unsigned char* __restrict__ imgU,
                                   unsigned char* __restrict__ imgV)
{
    int i = blockIdx.x * blockDim.x + threadIdx.x;
    if (i >= DD * OO) return;
    const float* w    = blockIdx.y ? wv : wu;
    unsigned char* im = blockIdx.y ? imgV : imgU;
    int k = i >> 6, n = i & 63;
    uint32_t off = (uint32_t)n * 256 + ((((k >> 3) ^ (n & 7))) << 4) + (k & 7) * 2;
    float s = 0.f;
#pragma unroll
    for (int r = 0; r < RR; r++) {
        s += w[r * DD * OO + i];
        __nv_bfloat16 h = __float2bfloat16_rn(s);
        __nv_bfloat16 l = __float2bfloat16_rn(s - __bfloat162float(h));
        *(__nv_bfloat16*)(im + r * 32768 + off)         = h;
        *(__nv_bfloat16*)(im + r * 32768 + 16384 + off) = l;
    }
}

// ---------------------------------------------------------------------------
// GEMM body: C[r][m][64] (fp16) = A[m][128] @ Wcum[r]; split-bf16 3-pass,
// double-buffered fragments. CTA 128x64, 256 threads, warp tile 32x32.
// ---------------------------------------------------------------------------
#define OFF_AH 0
#define OFF_AL 32768
#define OFF_BH 65536
#define OFF_BL 81920
#define GT_SMEM 98304

__device__ __forceinline__ void gemm_body(const float* __restrict__ A,
                                          const unsigned char* __restrict__ Bimg,
                                          __half* __restrict__ C, int M,
                                          int g, int m0, unsigned char* smem)
{
    const int tid  = threadIdx.x;
    const int wid  = tid >> 5;
    const int lane = tid & 31;

    // ---- A tile: fp32 load -> bf16 hi/lo swizzled smem ----
    for (int idx = tid; idx < 2048; idx += 256) {
        int m = idx >> 4, c = idx & 15, k0 = c << 3;
        float4 v0 = make_float4(0, 0, 0, 0), v1 = make_float4(0, 0, 0, 0);
        if (m0 + m < M) {
            const float* ap = A + (size_t)(m0 + m) * DD + k0;
            v0 = *(const float4*)ap;
            v1 = *(const float4*)(ap + 4);
        }
        float f[8] = {v0.x, v0.y, v0.z, v0.w, v1.x, v1.y, v1.z, v1.w};
        uint32_t hi[4], lo[4];
#pragma unroll
        for (int j = 0; j < 4; j++) {
            __nv_bfloat16 h0 = __float2bfloat16_rn(f[2 * j]);
            __nv_bfloat16 h1 = __float2bfloat16_rn(f[2 * j + 1]);
            __nv_bfloat16 l0 = __float2bfloat16_rn(f[2 * j]     - __bfloat162float(h0));
            __nv_bfloat16 l1 = __float2bfloat16_rn(f[2 * j + 1] - __bfloat162float(h1));
            hi[j] = (uint32_t)__bfloat16_as_ushort(h0) | ((uint32_t)__bfloat16_as_ushort(h1) << 16);
            lo[j] = (uint32_t)__bfloat16_as_ushort(l0) | ((uint32_t)__bfloat16_as_ushort(l1) << 16);
        }
        uint32_t off = (uint32_t)m * 256 + ((c ^ (m & 7)) << 4);
        *(uint4*)(smem + OFF_AH + off) = make_uint4(hi[0], hi[1], hi[2], hi[3]);
        *(uint4*)(smem + OFF_AL + off) = make_uint4(lo[0], lo[1], lo[2], lo[3]);
    }
    // ---- B: bulk copy pre-swizzled 32KB image for relation g ----
    {
        const uint4* src = (const uint4*)(Bimg + (size_t)g * 32768);
        uint4* dst = (uint4*)(smem + OFF_BH);
        for (int i = tid; i < 2048; i += 256) dst[i] = src[i];
    }
    __syncthreads();

    const int mbase = (wid >> 1) * 32;
    const int nbase = (wid & 1) * 32;

    float acc[2][4][4];
#pragma unroll
    for (int i = 0; i < 2; i++)
#pragma unroll
        for (int j = 0; j < 4; j++)
#pragma unroll
            for (int q = 0; q < 4; q++) acc[i][j][q] = 0.f;

    const uint32_t sb = smem_u32(smem);
    const int a_m  = mbase + (lane & 15);
    const int a_cb = lane >> 4;
    const int b_n  = nbase + (lane & 7) + ((lane >> 4) & 1) * 8;
    const int b_cb = (lane >> 3) & 1;

#pragma unroll
    for (int t = 0; t < 3; t++) {
        const uint32_t abase = sb + (t == 2 ? OFF_AL : OFF_AH);
        const uint32_t bbase = sb + (t == 1 ? OFF_BL : OFF_BH);
        uint32_t afr[2][2][4], bfr[2][2][4];   // [buf][mt|pr][frag]
        auto load_frags = [&](int ks, int buf) {
            const int c = ks * 2;
#pragma unroll
            for (int mt = 0; mt < 2; mt++) {
                int m = a_m + mt * 16, cc = c + a_cb;
                uint32_t ad = abase + (uint32_t)m * 256 + ((cc ^ (m & 7)) << 4);
                ldsm4(ad, afr[buf][mt][0], afr[buf][mt][1],
                          afr[buf][mt][2], afr[buf][mt][3]);
            }
#pragma unroll
            for (int pr = 0; pr < 2; pr++) {
                int n = b_n + pr * 16, cc = c + b_cb;
                uint32_t bd = bbase + (uint32_t)n * 256 + ((cc ^ (n & 7)) << 4);
                ldsm4(bd, bfr[buf][pr][0], bfr[buf][pr][1],
                          bfr[buf][pr][2], bfr[buf][pr][3]);
            }
        };
        load_frags(0, 0);
#pragma unroll
        for (int ks = 0; ks < 8; ks++) {
            const int cur = ks & 1;
            if (ks < 7) load_frags(ks + 1, cur ^ 1);
#pragma unroll
            for (int mt = 0; mt < 2; mt++)
#pragma unroll
                for (int nt = 0; nt < 4; nt++)
                    mma_bf16(acc[mt][nt], afr[cur][mt],
                             bfr[cur][nt >> 1][(nt & 1) * 2],
                             bfr[cur][nt >> 1][(nt & 1) * 2 + 1]);
        }
    }

    // ---- epilogue: fp16 half2 stores ----
    const int grp4 = lane >> 2, tg = lane & 3;
#pragma unroll
    for (int mt = 0; mt < 2; mt++)
#pragma unroll
        for (int nt = 0; nt < 4; nt++) {
            int row0 = m0 + mbase + mt * 16 + grp4;
            int col  = nbase + nt * 8 + tg * 2;
            if (row0 < M)
                *(__half2*)&C[((size_t)g * M + row0) * OO + col] =
                    __floats2half2_rn(acc[mt][nt][0], acc[mt][nt][1]);
            int row1 = row0 + 8;
            if (row1 < M)
                *(__half2*)&C[((size_t)g * M + row1) * OO + col] =
                    __floats2half2_rn(acc[mt][nt][2], acc[mt][nt][3]);
        }
}

// ---------------------------------------------------------------------------
// SpMM body: 8 lanes per edge, 4 edges per group; fp16 gather, fp32 red.
// block = 256 threads = 32 groups = 128 edges.
// ---------------------------------------------------------------------------
__device__ __forceinline__ void spmm_body(int rel, int blk,
                                          const int* __restrict__ rows,
                                          const int* __restrict__ cols,
                                          const float* __restrict__ vals,
                                          const __half* __restrict__ tmp,
                                          float* __restrict__ z)
{
    const int tid = threadIdx.x;
    const int grp = tid >> 3, l8 = tid & 7;
    const int e0  = blk * 128 + grp * 4;
    const size_t eo = (size_t)rel * EE + e0;

    int4 rw = make_int4(0, 0, 0, 0), cl = make_int4(0, 0, 0, 0);
    float4 vv = make_float4(0.f, 0.f, 0.f, 0.f);
    if (l8 == 0) {
        rw = *(const int4*)(rows + eo);
        cl = *(const int4*)(cols + eo);
        vv = *(const float4*)(vals + eo);
    }
    int re[4], ce[4];
    float ve[4];
    re[0] = __shfl_sync(0xffffffffu, rw.x, 0, 8);
    re[1] = __shfl_sync(0xffffffffu, rw.y, 0, 8);
    re[2] = __shfl_sync(0xffffffffu, rw.z, 0, 8);
    re[3] = __shfl_sync(0xffffffffu, rw.w, 0, 8);
    ce[0] = __shfl_sync(0xffffffffu, cl.x, 0, 8);
    ce[1] = __shfl_sync(0xffffffffu, cl.y, 0, 8);
    ce[2] = __shfl_sync(0xffffffffu, cl.z, 0, 8);
    ce[3] = __shfl_sync(0xffffffffu, cl.w, 0, 8);
    ve[0] = __shfl_sync(0xffffffffu, vv.x, 0, 8);
    ve[1] = __shfl_sync(0xffffffffu, vv.y, 0, 8);
    ve[2] = __shfl_sync(0xffffffffu, vv.z, 0, 8);
    ve[3] = __shfl_sync(0xffffffffu, vv.w, 0, 8);

    const uint4* tb = (const uint4*)(tmp + (size_t)rel * 100000 * OO);
    uint4 tv[4];
#pragma unroll
    for (int i = 0; i < 4; i++)
        tv[i] = __ldg(tb + (size_t)ce[i] * 8 + l8);

#pragma unroll
    for (int i = 0; i < 4; i++) {
        float2 f0 = __half22float2(*(__half2*)&tv[i].x);
        float2 f1 = __half22float2(*(__half2*)&tv[i].y);
        float2 f2 = __half22float2(*(__half2*)&tv[i].z);
        float2 f3 = __half22float2(*(__half2*)&tv[i].w);
        const float v = ve[i];
        float* dst = z + (size_t)re[i] * OO + l8 * 8;
        asm volatile("red.global.add.v4.f32 [%0], {%1, %2, %3, %4};"
                     :: "l"(dst),
                        "f"(f0.x * v), "f"(f0.y * v), "f"(f1.x * v), "f"(f1.y * v)
                     : "memory");
        asm volatile("red.global.add.v4.f32 [%0], {%1, %2, %3, %4};"
                     :: "l"(dst + 4),
                        "f"(f2.x * v), "f"(f2.y * v), "f"(f3.x * v), "f"(f3.y * v)
                     : "memory");
    }
}

// ---------------------------------------------------------------------------
// standalone kernels
// ---------------------------------------------------------------------------
__global__ void __launch_bounds__(256, 2)
gemm_tc_kernel(const float* __restrict__ A,
               const unsigned char* __restrict__ Bimg,
               __half* __restrict__ C, int M)
{
    extern __shared__ unsigned char smem[];
    gemm_body(A, Bimg, C, M, blockIdx.x, blockIdx.y * 128, smem);
}

__global__ void __launch_bounds__(256)
spmm_kernel(const int* __restrict__ rows, const int* __restrict__ cols,
            const float* __restrict__ vals, const __half* __restrict__ tmp,
            float* __restrict__ z)
{
    spmm_body(blockIdx.y, blockIdx.x, rows, cols, vals, tmp, z);
}

// ---------------------------------------------------------------------------
// merged kernel: spmm(V side -> z_u)  ||  gemm(U side -> tmpU)
// gemm blocks at bid % 7 == 6 (3910 of 28910), spmm elsewhere (25000).
// ---------------------------------------------------------------------------
__global__ void __launch_bounds__(256, 2)
merged_kernel(const float* __restrict__ xu,
              const unsigned char* __restrict__ BimgU,
              __half* __restrict__ tmpU,
              const int* __restrict__ rows, const int* __restrict__ cols,
              const float* __restrict__ vals,
              const __half* __restrict__ tmpV, float* __restrict__ z_u)
{
    extern __shared__ unsigned char smem[];
    const int bid = blockIdx.x;
    const int q = bid / 7, r7 = bid % 7;
    if (r7 == 6 && q < GEMM_BLOCKS) {
        gemm_body(xu, BimgU, tmpU, NU, q % RR, (q / RR) * 128, smem);
    } else {
        int sidx = bid - (q < GEMM_BLOCKS ? q : GEMM_BLOCKS);
        spmm_body(sidx / SPMM_BPR, sidx % SPMM_BPR, rows, cols, vals, tmpV, z_u);
    }
}

// ---------------------------------------------------------------------------
// zero / relu
// ---------------------------------------------------------------------------
__global__ void zero_kernel(float4* __restrict__ p, int n4)
{
    int i = blockIdx.x * blockDim.x + threadIdx.x;
    if (i < n4) p[i] = make_float4(0.f, 0.f, 0.f, 0.f);
}
__global__ void relu_kernel(float4* __restrict__ p, int n4)
{
    int i = blockIdx.x * blockDim.x + threadIdx.x;
    if (i < n4) {
        float4 v = p[i];
        v.x = fmaxf(v.x, 0.f); v.y = fmaxf(v.y, 0.f);
        v.z = fmaxf(v.z, 0.f); v.w = fmaxf(v.w, 0.f);
        p[i] = v;
    }
}

// ---------------------------------------------------------------------------
// kernel_launch
// ---------------------------------------------------------------------------
extern "C" void kernel_launch(void* const* d_in, const int* in_sizes, int n_in,
                              void* d_out, int out_size)
{
    const float* x_u  = (const float*)d_in[0];
    const float* x_v  = (const float*)d_in[1];
    const int*   srow = (const int*)d_in[2];
    const int*   scol = (const int*)d_in[3];
    const float* sval = (const float*)d_in[4];
    const float* wu   = (const float*)d_in[5];
    const float* wv   = (const float*)d_in[6];

    float* out = (float*)d_out;
    float* z_u = out;
    float* z_v = out + (size_t)NU * OO;

    __half *tmpU, *tmpV;
    unsigned char *BiU, *BiV;
    cudaGetSymbolAddress((void**)&tmpU, g_tmpU);
    cudaGetSymbolAddress((void**)&tmpV, g_tmpV);
    cudaGetSymbolAddress((void**)&BiU, g_BimgU);
    cudaGetSymbolAddress((void**)&BiV, g_BimgV);

    cudaFuncSetAttribute(gemm_tc_kernel,
                         cudaFuncAttributeMaxDynamicSharedMemorySize, GT_SMEM);
    cudaFuncSetAttribute(merged_kernel,
                         cudaFuncAttributeMaxDynamicSharedMemorySize, GT_SMEM);

    const int n4 = (NU * OO + NVV * OO) / 4;
    zero_kernel<<<(n4 + 255) / 256, 256>>>((float4*)out, n4);

    cumsum_pack_kernel<<<dim3((DD * OO + 255) / 256, 2), 256>>>(wu, wv, BiU, BiV);

    // 1) v-side GEMM
    gemm_tc_kernel<<<dim3(RR, GEMM_TILES), 256, GT_SMEM>>>(x_v, BiV, tmpV, NVV);
    // 2) spmmV (tmpV -> z_u) overlapped with u-side GEMM (x_u -> tmpU)
    merged_kernel<<<MERGED_GRID, 256, GT_SMEM>>>(x_u, BiU, tmpU,
                                                 srow, scol, sval, tmpV, z_u);
    // 3) spmmU (tmpU -> z_v)
    spmm_kernel<<<dim3(SPMM_BPR, RR), 256>>>(scol, srow, sval, tmpU, z_v);

    relu_kernel<<<(n4 + 255) / 256, 256>>>((float4*)out, n4);
}

// round 6
// speedup vs baseline: 1.1253x; 1.1253x over previous
#include <cuda_runtime.h>
#include <cuda_bf16.h>
#include <cuda_fp16.h>
#include <cstdint>
#include <cstddef>

#define NU 100000
#define NVV 100000
#define DD 128
#define RR 5
#define OO 64
#define EE 640000

#define GEMM_TILES 782                 /* ceil(100000/128) */
#define SPMM_BPR   5000                /* 640000 / 128 edges per block */

// ---------------------------------------------------------------------------
// Scratch (static device globals) — tmp in fp16
// ---------------------------------------------------------------------------
__device__ __half g_tmpU[(size_t)RR * NU * OO];   // [r][n][64]
__device__ __half g_tmpV[(size_t)RR * NVV * OO];
// Pre-swizzled bf16 B images: per relation 32KB = hi 16KB | lo 16KB.
__device__ unsigned char g_BimgU[RR * 32768];
__device__ unsigned char g_BimgV[RR * 32768];

// ---------------------------------------------------------------------------
// helpers
// ---------------------------------------------------------------------------
__device__ __forceinline__ uint32_t smem_u32(const void* p) {
    uint32_t a;
    asm("{ .reg .u64 t; cvta.to.shared.u64 t, %1; cvt.u32.u64 %0, t; }"
        : "=r"(a) : "l"(p));
    return a;
}
__device__ __forceinline__ void ldsm4(uint32_t addr, uint32_t& r0, uint32_t& r1,
                                      uint32_t& r2, uint32_t& r3) {
    asm volatile("ldmatrix.sync.aligned.m8n8.x4.shared.b16 {%0,%1,%2,%3}, [%4];"
                 : "=r"(r0), "=r"(r1), "=r"(r2), "=r"(r3) : "r"(addr));
}
__device__ __forceinline__ void mma_bf16(float* d, const uint32_t* a,
                                         uint32_t b0, uint32_t b1) {
    asm volatile(
        "mma.sync.aligned.m16n8k16.row.col.f32.bf16.bf16.f32 "
        "{%0,%1,%2,%3}, {%4,%5,%6,%7}, {%8,%9}, {%0,%1,%2,%3};"
        : "+f"(d[0]), "+f"(d[1]), "+f"(d[2]), "+f"(d[3])
        : "r"(a[0]), "r"(a[1]), "r"(a[2]), "r"(a[3]), "r"(b0), "r"(b1));
}

// ---------------------------------------------------------------------------
// cumsum weights + pack swizzled bf16 hi/lo B images (k = d, n = o)
// ---------------------------------------------------------------------------
__global__ void cumsum_pack_kernel(const float* __restrict__ wu,
                                   const float* __restrict__ wv,
                                   unsigned char* __restrict__ imgU,
                                   unsigned char* __restrict__ imgV)
{
    int i = blockIdx.x * blockDim.x + threadIdx.x;
    if (i >= DD * OO) return;
    const float* w    = blockIdx.y ? wv : wu;
    unsigned char* im = blockIdx.y ? imgV : imgU;
    int k = i >> 6, n = i & 63;
    uint32_t off = (uint32_t)n * 256 + ((((k >> 3) ^ (n & 7))) << 4) + (k & 7) * 2;
    float s = 0.f;
#pragma unroll
    for (int r = 0; r < RR; r++) {
        s += w[r * DD * OO + i];
        __nv_bfloat16 h = __float2bfloat16_rn(s);
        __nv_bfloat16 l = __float2bfloat16_rn(s - __bfloat162float(h));
        *(__nv_bfloat16*)(im + r * 32768 + off)         = h;
        *(__nv_bfloat16*)(im + r * 32768 + 16384 + off) = l;
    }
}

// ---------------------------------------------------------------------------
// GEMM: one CTA = 128-row tile, loops over all 5 relations (A loaded once).
// Split-bf16 3-pass, double-buffered fragments. 256 thr, warp tile 32x32.
// SMEM: Ah 32KB | Al 32KB | B(hi|lo) 32KB = 96KB -> 2 CTAs/SM.
// ---------------------------------------------------------------------------
#define OFF_AH 0
#define OFF_AL 32768
#define OFF_BH 65536
#define OFF_BL 81920
#define GT_SMEM 98304

__global__ void __launch_bounds__(256, 2)
gemm_tc_kernel(const float* __restrict__ A,
               const unsigned char* __restrict__ Bimg,
               __half* __restrict__ C, int M)
{
    extern __shared__ unsigned char smem[];
    const int tid  = threadIdx.x;
    const int wid  = tid >> 5;
    const int lane = tid & 31;
    const int m0   = blockIdx.x * 128;

    // ---- A tile: fp32 load -> bf16 hi/lo swizzled smem (ONCE) ----
    for (int idx = tid; idx < 2048; idx += 256) {
        int m = idx >> 4, c = idx & 15, k0 = c << 3;
        float4 v0 = make_float4(0, 0, 0, 0), v1 = make_float4(0, 0, 0, 0);
        if (m0 + m < M) {
            const float* ap = A + (size_t)(m0 + m) * DD + k0;
            v0 = *(const float4*)ap;
            v1 = *(const float4*)(ap + 4);
        }
        float f[8] = {v0.x, v0.y, v0.z, v0.w, v1.x, v1.y, v1.z, v1.w};
        uint32_t hi[4], lo[4];
#pragma unroll
        for (int j = 0; j < 4; j++) {
            __nv_bfloat16 h0 = __float2bfloat16_rn(f[2 * j]);
            __nv_bfloat16 h1 = __float2bfloat16_rn(f[2 * j + 1]);
            __nv_bfloat16 l0 = __float2bfloat16_rn(f[2 * j]     - __bfloat162float(h0));
            __nv_bfloat16 l1 = __float2bfloat16_rn(f[2 * j + 1] - __bfloat162float(h1));
            hi[j] = (uint32_t)__bfloat16_as_ushort(h0) | ((uint32_t)__bfloat16_as_ushort(h1) << 16);
            lo[j] = (uint32_t)__bfloat16_as_ushort(l0) | ((uint32_t)__bfloat16_as_ushort(l1) << 16);
        }
        uint32_t off = (uint32_t)m * 256 + ((c ^ (m & 7)) << 4);
        *(uint4*)(smem + OFF_AH + off) = make_uint4(hi[0], hi[1], hi[2], hi[3]);
        *(uint4*)(smem + OFF_AL + off) = make_uint4(lo[0], lo[1], lo[2], lo[3]);
    }

    const int mbase = (wid >> 1) * 32;
    const int nbase = (wid & 1) * 32;
    const uint32_t sb = smem_u32(smem);
    const int a_m  = mbase + (lane & 15);
    const int a_cb = lane >> 4;
    const int b_n  = nbase + (lane & 7) + ((lane >> 4) & 1) * 8;
    const int b_cb = (lane >> 3) & 1;
    const int grp4 = lane >> 2, tg = lane & 3;

    for (int g = 0; g < RR; g++) {
        // ---- copy pre-swizzled 32KB B image for relation g ----
        {
            const uint4* src = (const uint4*)(Bimg + (size_t)g * 32768);
            uint4* dst = (uint4*)(smem + OFF_BH);
            for (int i = tid; i < 2048; i += 256) dst[i] = src[i];
        }
        __syncthreads();

        float acc[2][4][4];
#pragma unroll
        for (int i = 0; i < 2; i++)
#pragma unroll
            for (int j = 0; j < 4; j++)
#pragma unroll
                for (int q = 0; q < 4; q++) acc[i][j][q] = 0.f;

#pragma unroll
        for (int t = 0; t < 3; t++) {
            const uint32_t abase = sb + (t == 2 ? OFF_AL : OFF_AH);
            const uint32_t bbase = sb + (t == 1 ? OFF_BL : OFF_BH);
            uint32_t afr[2][2][4], bfr[2][2][4];   // [buf][mt|pr][frag]
            auto load_frags = [&](int ks, int buf) {
                const int c = ks * 2;
#pragma unroll
                for (int mt = 0; mt < 2; mt++) {
                    int m = a_m + mt * 16, cc = c + a_cb;
                    uint32_t ad = abase + (uint32_t)m * 256 + ((cc ^ (m & 7)) << 4);
                    ldsm4(ad, afr[buf][mt][0], afr[buf][mt][1],
                              afr[buf][mt][2], afr[buf][mt][3]);
                }
#pragma unroll
                for (int pr = 0; pr < 2; pr++) {
                    int n = b_n + pr * 16, cc = c + b_cb;
                    uint32_t bd = bbase + (uint32_t)n * 256 + ((cc ^ (n & 7)) << 4);
                    ldsm4(bd, bfr[buf][pr][0], bfr[buf][pr][1],
                              bfr[buf][pr][2], bfr[buf][pr][3]);
                }
            };
            load_frags(0, 0);
#pragma unroll
            for (int ks = 0; ks < 8; ks++) {
                const int cur = ks & 1;
                if (ks < 7) load_frags(ks + 1, cur ^ 1);
#pragma unroll
                for (int mt = 0; mt < 2; mt++)
#pragma unroll
                    for (int nt = 0; nt < 4; nt++)
                        mma_bf16(acc[mt][nt], afr[cur][mt],
                                 bfr[cur][nt >> 1][(nt & 1) * 2],
                                 bfr[cur][nt >> 1][(nt & 1) * 2 + 1]);
            }
        }

        // ---- epilogue: fp16 half2 stores ----
#pragma unroll
        for (int mt = 0; mt < 2; mt++)
#pragma unroll
            for (int nt = 0; nt < 4; nt++) {
                int row0 = m0 + mbase + mt * 16 + grp4;
                int col  = nbase + nt * 8 + tg * 2;
                if (row0 < M)
                    *(__half2*)&C[((size_t)g * M + row0) * OO + col] =
                        __floats2half2_rn(acc[mt][nt][0], acc[mt][nt][1]);
                int row1 = row0 + 8;
                if (row1 < M)
                    *(__half2*)&C[((size_t)g * M + row1) * OO + col] =
                        __floats2half2_rn(acc[mt][nt][2], acc[mt][nt][3]);
            }
        __syncthreads();   // before overwriting B for next relation
    }
}

// ---------------------------------------------------------------------------
// SpMM: 8 lanes/edge, 4 edges/group; fp16 gather, fp32 red.global.add.
// block = 256 threads = 128 edges. grid = (5000, RR).
// ---------------------------------------------------------------------------
__global__ void __launch_bounds__(256)
spmm_kernel(const int* __restrict__ rows, const int* __restrict__ cols,
            const float* __restrict__ vals, const __half* __restrict__ tmp,
            float* __restrict__ z)
{
    const int rel = blockIdx.y;
    const int tid = threadIdx.x;
    const int grp = tid >> 3, l8 = tid & 7;
    const int e0  = blockIdx.x * 128 + grp * 4;
    const size_t eo = (size_t)rel * EE + e0;

    int4 rw = make_int4(0, 0, 0, 0), cl = make_int4(0, 0, 0, 0);
    float4 vv = make_float4(0.f, 0.f, 0.f, 0.f);
    if (l8 == 0) {
        rw = *(const int4*)(rows + eo);
        cl = *(const int4*)(cols + eo);
        vv = *(const float4*)(vals + eo);
    }
    int re[4], ce[4];
    float ve[4];
    re[0] = __shfl_sync(0xffffffffu, rw.x, 0, 8);
    re[1] = __shfl_sync(0xffffffffu, rw.y, 0, 8);
    re[2] = __shfl_sync(0xffffffffu, rw.z, 0, 8);
    re[3] = __shfl_sync(0xffffffffu, rw.w, 0, 8);
    ce[0] = __shfl_sync(0xffffffffu, cl.x, 0, 8);
    ce[1] = __shfl_sync(0xffffffffu, cl.y, 0, 8);
    ce[2] = __shfl_sync(0xffffffffu, cl.z, 0, 8);
    ce[3] = __shfl_sync(0xffffffffu, cl.w, 0, 8);
    ve[0] = __shfl_sync(0xffffffffu, vv.x, 0, 8);
    ve[1] = __shfl_sync(0xffffffffu, vv.y, 0, 8);
    ve[2] = __shfl_sync(0xffffffffu, vv.z, 0, 8);
    ve[3] = __shfl_sync(0xffffffffu, vv.w, 0, 8);

    const uint4* tb = (const uint4*)(tmp + (size_t)rel * 100000 * OO);
    uint4 tv[4];
#pragma unroll
    for (int i = 0; i < 4; i++)
        tv[i] = __ldg(tb + (size_t)ce[i] * 8 + l8);

#pragma unroll
    for (int i = 0; i < 4; i++) {
        float2 f0 = __half22float2(*(__half2*)&tv[i].x);
        float2 f1 = __half22float2(*(__half2*)&tv[i].y);
        float2 f2 = __half22float2(*(__half2*)&tv[i].z);
        float2 f3 = __half22float2(*(__half2*)&tv[i].w);
        const float v = ve[i];
        float* dst = z + (size_t)re[i] * OO + l8 * 8;
        asm volatile("red.global.add.v4.f32 [%0], {%1, %2, %3, %4};"
                     :: "l"(dst),
                        "f"(f0.x * v), "f"(f0.y * v), "f"(f1.x * v), "f"(f1.y * v)
                     : "memory");
        asm volatile("red.global.add.v4.f32 [%0], {%1, %2, %3, %4};"
                     :: "l"(dst + 4),
                        "f"(f2.x * v), "f"(f2.y * v), "f"(f3.x * v), "f"(f3.y * v)
                     : "memory");
    }
}

// ---------------------------------------------------------------------------
// zero / relu
// ---------------------------------------------------------------------------
__global__ void zero_kernel(float4* __restrict__ p, int n4)
{
    int i = blockIdx.x * blockDim.x + threadIdx.x;
    if (i < n4) p[i] = make_float4(0.f, 0.f, 0.f, 0.f);
}
__global__ void relu_kernel(float4* __restrict__ p, int n4)
{
    int i = blockIdx.x * blockDim.x + threadIdx.x;
    if (i < n4) {
        float4 v = p[i];
        v.x = fmaxf(v.x, 0.f); v.y = fmaxf(v.y, 0.f);
        v.z = fmaxf(v.z, 0.f); v.w = fmaxf(v.w, 0.f);
        p[i] = v;
    }
}

// ---------------------------------------------------------------------------
// kernel_launch
// ---------------------------------------------------------------------------
extern "C" void kernel_launch(void* const* d_in, const int* in_sizes, int n_in,
                              void* d_out, int out_size)
{
    const float* x_u  = (const float*)d_in[0];
    const float* x_v  = (const float*)d_in[1];
    const int*   srow = (const int*)d_in[2];
    const int*   scol = (const int*)d_in[3];
    const float* sval = (const float*)d_in[4];
    const float* wu   = (const float*)d_in[5];
    const float* wv   = (const float*)d_in[6];

    float* out = (float*)d_out;
    float* z_u = out;
    float* z_v = out + (size_t)NU * OO;

    __half *tmpU, *tmpV;
    unsigned char *BiU, *BiV;
    cudaGetSymbolAddress((void**)&tmpU, g_tmpU);
    cudaGetSymbolAddress((void**)&tmpV, g_tmpV);
    cudaGetSymbolAddress((void**)&BiU, g_BimgU);
    cudaGetSymbolAddress((void**)&BiV, g_BimgV);

    cudaFuncSetAttribute(gemm_tc_kernel,
                         cudaFuncAttributeMaxDynamicSharedMemorySize, GT_SMEM);

    const int n4 = (NU * OO + NVV * OO) / 4;
    zero_kernel<<<(n4 + 255) / 256, 256>>>((float4*)out, n4);

    cumsum_pack_kernel<<<dim3((DD * OO + 255) / 256, 2), 256>>>(wu, wv, BiU, BiV);

    // v side: GEMM tmpV then scatter into z_u (tmpV hot in L2)
    gemm_tc_kernel<<<GEMM_TILES, 256, GT_SMEM>>>(x_v, BiV, tmpV, NVV);
    spmm_kernel<<<dim3(SPMM_BPR, RR), 256>>>(srow, scol, sval, tmpV, z_u);

    // u side
    gemm_tc_kernel<<<GEMM_TILES, 256, GT_SMEM>>>(x_u, BiU, tmpU, NU);
    spmm_kernel<<<dim3(SPMM_BPR, RR), 256>>>(scol, srow, sval, tmpU, z_v);

    relu_kernel<<<(n4 + 255) / 256, 256>>>((float4*)out, n4);
}

// round 7
// speedup vs baseline: 1.3397x; 1.1906x over previous
#include <cuda_runtime.h>
#include <cuda_bf16.h>
#include <cuda_fp16.h>
#include <cstdint>
#include <cstddef>

#define NU 100000
#define NVV 100000
#define DD 128
#define RR 5
#define OO 64
#define EE 640000

#define GEMM_TILES 782                 /* ceil(100000/128) */
#define SPMM_BPR   20000               /* 640000 / 32 edges per block */

// ---------------------------------------------------------------------------
// Scratch (static device globals) — tmp in fp16
// ---------------------------------------------------------------------------
__device__ __half g_tmpU[(size_t)RR * NU * OO];   // [r][n][64]
__device__ __half g_tmpV[(size_t)RR * NVV * OO];
// Pre-swizzled bf16 B images: per relation 32KB = hi 16KB | lo 16KB.
__device__ unsigned char g_BimgU[RR * 32768];
__device__ unsigned char g_BimgV[RR * 32768];

// ---------------------------------------------------------------------------
// helpers
// ---------------------------------------------------------------------------
__device__ __forceinline__ uint32_t smem_u32(const void* p) {
    uint32_t a;
    asm("{ .reg .u64 t; cvta.to.shared.u64 t, %1; cvt.u32.u64 %0, t; }"
        : "=r"(a) : "l"(p));
    return a;
}
__device__ __forceinline__ void ldsm4(uint32_t addr, uint32_t& r0, uint32_t& r1,
                                      uint32_t& r2, uint32_t& r3) {
    asm volatile("ldmatrix.sync.aligned.m8n8.x4.shared.b16 {%0,%1,%2,%3}, [%4];"
                 : "=r"(r0), "=r"(r1), "=r"(r2), "=r"(r3) : "r"(addr));
}
__device__ __forceinline__ void mma_bf16(float* d, const uint32_t* a,
                                         uint32_t b0, uint32_t b1) {
    asm volatile(
        "mma.sync.aligned.m16n8k16.row.col.f32.bf16.bf16.f32 "
        "{%0,%1,%2,%3}, {%4,%5,%6,%7}, {%8,%9}, {%0,%1,%2,%3};"
        : "+f"(d[0]), "+f"(d[1]), "+f"(d[2]), "+f"(d[3])
        : "r"(a[0]), "r"(a[1]), "r"(a[2]), "r"(a[3]), "r"(b0), "r"(b1));
}

// ---------------------------------------------------------------------------
// cumsum weights + pack swizzled bf16 hi/lo B images (k = d, n = o)
// ---------------------------------------------------------------------------
__global__ void cumsum_pack_kernel(const float* __restrict__ wu,
                                   const float* __restrict__ wv,
                                   unsigned char* __restrict__ imgU,
                                   unsigned char* __restrict__ imgV)
{
    int i = blockIdx.x * blockDim.x + threadIdx.x;
    if (i >= DD * OO) return;
    const float* w    = blockIdx.y ? wv : wu;
    unsigned char* im = blockIdx.y ? imgV : imgU;
    int k = i >> 6, n = i & 63;
    uint32_t off = (uint32_t)n * 256 + ((((k >> 3) ^ (n & 7))) << 4) + (k & 7) * 2;
    float s = 0.f;
#pragma unroll
    for (int r = 0; r < RR; r++) {
        s += w[r * DD * OO + i];
        __nv_bfloat16 h = __float2bfloat16_rn(s);
        __nv_bfloat16 l = __float2bfloat16_rn(s - __bfloat162float(h));
        *(__nv_bfloat16*)(im + r * 32768 + off)         = h;
        *(__nv_bfloat16*)(im + r * 32768 + 16384 + off) = l;
    }
}

// ---------------------------------------------------------------------------
// GEMM: one CTA = 128-row tile, loops over all 5 relations (A loaded once).
// Split-bf16 3-pass, double-buffered fragments. 256 thr, warp tile 32x32.
// SMEM: Ah 32KB | Al 32KB | B(hi|lo) 32KB = 96KB -> 2 CTAs/SM.
// ---------------------------------------------------------------------------
#define OFF_AH 0
#define OFF_AL 32768
#define OFF_BH 65536
#define OFF_BL 81920
#define GT_SMEM 98304

__global__ void __launch_bounds__(256, 2)
gemm_tc_kernel(const float* __restrict__ A,
               const unsigned char* __restrict__ Bimg,
               __half* __restrict__ C, int M)
{
    extern __shared__ unsigned char smem[];
    const int tid  = threadIdx.x;
    const int wid  = tid >> 5;
    const int lane = tid & 31;
    const int m0   = blockIdx.x * 128;

    // ---- A tile: fp32 load -> bf16 hi/lo swizzled smem (ONCE) ----
    for (int idx = tid; idx < 2048; idx += 256) {
        int m = idx >> 4, c = idx & 15, k0 = c << 3;
        float4 v0 = make_float4(0, 0, 0, 0), v1 = make_float4(0, 0, 0, 0);
        if (m0 + m < M) {
            const float* ap = A + (size_t)(m0 + m) * DD + k0;
            v0 = *(const float4*)ap;
            v1 = *(const float4*)(ap + 4);
        }
        float f[8] = {v0.x, v0.y, v0.z, v0.w, v1.x, v1.y, v1.z, v1.w};
        uint32_t hi[4], lo[4];
#pragma unroll
        for (int j = 0; j < 4; j++) {
            __nv_bfloat16 h0 = __float2bfloat16_rn(f[2 * j]);
            __nv_bfloat16 h1 = __float2bfloat16_rn(f[2 * j + 1]);
            __nv_bfloat16 l0 = __float2bfloat16_rn(f[2 * j]     - __bfloat162float(h0));
            __nv_bfloat16 l1 = __float2bfloat16_rn(f[2 * j + 1] - __bfloat162float(h1));
            hi[j] = (uint32_t)__bfloat16_as_ushort(h0) | ((uint32_t)__bfloat16_as_ushort(h1) << 16);
            lo[j] = (uint32_t)__bfloat16_as_ushort(l0) | ((uint32_t)__bfloat16_as_ushort(l1) << 16);
        }
        uint32_t off = (uint32_t)m * 256 + ((c ^ (m & 7)) << 4);
        *(uint4*)(smem + OFF_AH + off) = make_uint4(hi[0], hi[1], hi[2], hi[3]);
        *(uint4*)(smem + OFF_AL + off) = make_uint4(lo[0], lo[1], lo[2], lo[3]);
    }

    const int mbase = (wid >> 1) * 32;
    const int nbase = (wid & 1) * 32;
    const uint32_t sb = smem_u32(smem);
    const int a_m  = mbase + (lane & 15);
    const int a_cb = lane >> 4;
    const int b_n  = nbase + (lane & 7) + ((lane >> 4) & 1) * 8;
    const int b_cb = (lane >> 3) & 1;
    const int grp4 = lane >> 2, tg = lane & 3;

    for (int g = 0; g < RR; g++) {
        // ---- copy pre-swizzled 32KB B image for relation g ----
        {
            const uint4* src = (const uint4*)(Bimg + (size_t)g * 32768);
            uint4* dst = (uint4*)(smem + OFF_BH);
            for (int i = tid; i < 2048; i += 256) dst[i] = src[i];
        }
        __syncthreads();

        float acc[2][4][4];
#pragma unroll
        for (int i = 0; i < 2; i++)
#pragma unroll
            for (int j = 0; j < 4; j++)
#pragma unroll
                for (int q = 0; q < 4; q++) acc[i][j][q] = 0.f;

#pragma unroll
        for (int t = 0; t < 3; t++) {
            const uint32_t abase = sb + (t == 2 ? OFF_AL : OFF_AH);
            const uint32_t bbase = sb + (t == 1 ? OFF_BL : OFF_BH);
            uint32_t afr[2][2][4], bfr[2][2][4];   // [buf][mt|pr][frag]
            auto load_frags = [&](int ks, int buf) {
                const int c = ks * 2;
#pragma unroll
                for (int mt = 0; mt < 2; mt++) {
                    int m = a_m + mt * 16, cc = c + a_cb;
                    uint32_t ad = abase + (uint32_t)m * 256 + ((cc ^ (m & 7)) << 4);
                    ldsm4(ad, afr[buf][mt][0], afr[buf][mt][1],
                              afr[buf][mt][2], afr[buf][mt][3]);
                }
#pragma unroll
                for (int pr = 0; pr < 2; pr++) {
                    int n = b_n + pr * 16, cc = c + b_cb;
                    uint32_t bd = bbase + (uint32_t)n * 256 + ((cc ^ (n & 7)) << 4);
                    ldsm4(bd, bfr[buf][pr][0], bfr[buf][pr][1],
                              bfr[buf][pr][2], bfr[buf][pr][3]);
                }
            };
            load_frags(0, 0);
#pragma unroll
            for (int ks = 0; ks < 8; ks++) {
                const int cur = ks & 1;
                if (ks < 7) load_frags(ks + 1, cur ^ 1);
#pragma unroll
                for (int mt = 0; mt < 2; mt++)
#pragma unroll
                    for (int nt = 0; nt < 4; nt++)
                        mma_bf16(acc[mt][nt], afr[cur][mt],
                                 bfr[cur][nt >> 1][(nt & 1) * 2],
                                 bfr[cur][nt >> 1][(nt & 1) * 2 + 1]);
            }
        }

        // ---- epilogue: fp16 half2 stores ----
#pragma unroll
        for (int mt = 0; mt < 2; mt++)
#pragma unroll
            for (int nt = 0; nt < 4; nt++) {
                int row0 = m0 + mbase + mt * 16 + grp4;
                int col  = nbase + nt * 8 + tg * 2;
                if (row0 < M)
                    *(__half2*)&C[((size_t)g * M + row0) * OO + col] =
                        __floats2half2_rn(acc[mt][nt][0], acc[mt][nt][1]);
                int row1 = row0 + 8;
                if (row1 < M)
                    *(__half2*)&C[((size_t)g * M + row1) * OO + col] =
                        __floats2half2_rn(acc[mt][nt][2], acc[mt][nt][3]);
            }
        __syncthreads();   // before overwriting B for next relation
    }
}

// ---------------------------------------------------------------------------
// SpMM: R4 shape (16 lanes/edge, 2 edges/group) with fp16 gathers.
// Lane loads uint2 (4 halves), one red.v4.f32 per lane per edge.
// block = 256 threads = 32 edges. grid = (20000, RR).
// ---------------------------------------------------------------------------
__global__ void __launch_bounds__(256)
spmm_kernel(const int* __restrict__ rows, const int* __restrict__ cols,
            const float* __restrict__ vals, const __half* __restrict__ tmp,
            float* __restrict__ z)
{
    const int rel = blockIdx.y;
    const int grp = threadIdx.x >> 4;
    const int l16 = threadIdx.x & 15;
    const int e   = blockIdx.x * 32 + grp * 2;
    const size_t eo = (size_t)rel * EE + e;

    int2 rw = make_int2(0, 0), cl = make_int2(0, 0);
    float2 vv = make_float2(0.f, 0.f);
    if (l16 == 0) {
        rw = *(const int2*)(rows + eo);
        cl = *(const int2*)(cols + eo);
        vv = *(const float2*)(vals + eo);
    }
    int   row0 = __shfl_sync(0xffffffffu, rw.x, 0, 16);
    int   row1 = __shfl_sync(0xffffffffu, rw.y, 0, 16);
    int   col0 = __shfl_sync(0xffffffffu, cl.x, 0, 16);
    int   col1 = __shfl_sync(0xffffffffu, cl.y, 0, 16);
    float v0   = __shfl_sync(0xffffffffu, vv.x, 0, 16);
    float v1   = __shfl_sync(0xffffffffu, vv.y, 0, 16);

    const uint2* tb = (const uint2*)(tmp + (size_t)rel * 100000 * OO);
    uint2 t0 = __ldg(tb + (size_t)col0 * 16 + l16);
    uint2 t1 = __ldg(tb + (size_t)col1 * 16 + l16);

    float2 a0 = __half22float2(*(__half2*)&t0.x);
    float2 a1 = __half22float2(*(__half2*)&t0.y);
    float2 b0 = __half22float2(*(__half2*)&t1.x);
    float2 b1 = __half22float2(*(__half2*)&t1.y);

    float* d0 = z + (size_t)row0 * OO + (l16 << 2);
    float* d1 = z + (size_t)row1 * OO + (l16 << 2);
    asm volatile("red.global.add.v4.f32 [%0], {%1, %2, %3, %4};"
                 :: "l"(d0), "f"(a0.x * v0), "f"(a0.y * v0),
                    "f"(a1.x * v0), "f"(a1.y * v0)
                 : "memory");
    asm volatile("red.global.add.v4.f32 [%0], {%1, %2, %3, %4};"
                 :: "l"(d1), "f"(b0.x * v1), "f"(b0.y * v1),
                    "f"(b1.x * v1), "f"(b1.y * v1)
                 : "memory");
}

// ---------------------------------------------------------------------------
// zero / relu
// ---------------------------------------------------------------------------
__global__ void zero_kernel(float4* __restrict__ p, int n4)
{
    int i = blockIdx.x * blockDim.x + threadIdx.x;
    if (i < n4) p[i] = make_float4(0.f, 0.f, 0.f, 0.f);
}
__global__ void relu_kernel(float4* __restrict__ p, int n4)
{
    int i = blockIdx.x * blockDim.x + threadIdx.x;
    if (i < n4) {
        float4 v = p[i];
        v.x = fmaxf(v.x, 0.f); v.y = fmaxf(v.y, 0.f);
        v.z = fmaxf(v.z, 0.f); v.w = fmaxf(v.w, 0.f);
        p[i] = v;
    }
}

// ---------------------------------------------------------------------------
// kernel_launch
// ---------------------------------------------------------------------------
extern "C" void kernel_launch(void* const* d_in, const int* in_sizes, int n_in,
                              void* d_out, int out_size)
{
    const float* x_u  = (const float*)d_in[0];
    const float* x_v  = (const float*)d_in[1];
    const int*   srow = (const int*)d_in[2];
    const int*   scol = (const int*)d_in[3];
    const float* sval = (const float*)d_in[4];
    const float* wu   = (const float*)d_in[5];
    const float* wv   = (const float*)d_in[6];

    float* out = (float*)d_out;
    float* z_u = out;
    float* z_v = out + (size_t)NU * OO;

    __half *tmpU, *tmpV;
    unsigned char *BiU, *BiV;
    cudaGetSymbolAddress((void**)&tmpU, g_tmpU);
    cudaGetSymbolAddress((void**)&tmpV, g_tmpV);
    cudaGetSymbolAddress((void**)&BiU, g_BimgU);
    cudaGetSymbolAddress((void**)&BiV, g_BimgV);

    cudaFuncSetAttribute(gemm_tc_kernel,
                         cudaFuncAttributeMaxDynamicSharedMemorySize, GT_SMEM);

    const int n4 = (NU * OO + NVV * OO) / 4;
    zero_kernel<<<(n4 + 255) / 256, 256>>>((float4*)out, n4);

    cumsum_pack_kernel<<<dim3((DD * OO + 255) / 256, 2), 256>>>(wu, wv, BiU, BiV);

    // v side: GEMM tmpV then scatter into z_u (tmpV hot in L2)
    gemm_tc_kernel<<<GEMM_TILES, 256, GT_SMEM>>>(x_v, BiV, tmpV, NVV);
    spmm_kernel<<<dim3(SPMM_BPR, RR), 256>>>(srow, scol, sval, tmpV, z_u);

    // u side
    gemm_tc_kernel<<<GEMM_TILES, 256, GT_SMEM>>>(x_u, BiU, tmpU, NU);
    spmm_kernel<<<dim3(SPMM_BPR, RR), 256>>>(scol, srow, sval, tmpU, z_v);

    relu_kernel<<<(n4 + 255) / 256, 256>>>((float4*)out, n4);
}